// round 1
// baseline (speedup 1.0000x reference)
#include <cuda_runtime.h>

#define ROWS 32
#define HD 512
#define DD 64
#define NT 256

// smem layout (floats): xs[32*64] | h0[32*512] | h1[32*512] | d[32*512]
// total = 2048 + 3*16384 = 51200 floats = 204800 bytes

__device__ __forceinline__ float4 ld4(const float* __restrict__ p) {
    return *reinterpret_cast<const float4*>(p);
}

// Forward layer: out = tanh(prev @ W + b); prev smem [ROWS][K], W global [K][512].
// If LAST: out = (1 - t*t) * W3[c]   (this is d2, seed of the backward pass)
template<int K, bool LAST>
__device__ __forceinline__ void fwd_layer(
    const float* __restrict__ prev,
    const float* __restrict__ W,
    const float* __restrict__ b,
    const float* __restrict__ W3,
    float* __restrict__ out,
    int tx, int ty)
{
    float4 acc[4][4];
#pragma unroll
    for (int i = 0; i < 4; i++)
#pragma unroll
        for (int j = 0; j < 4; j++)
            acc[i][j] = make_float4(0.f, 0.f, 0.f, 0.f);

    for (int k = 0; k < K; k += 4) {
        float a_[4][4];
#pragma unroll
        for (int i = 0; i < 4; i++) {
            float4 a4 = ld4(&prev[(ty + 8 * i) * K + k]);
            a_[i][0] = a4.x; a_[i][1] = a4.y; a_[i][2] = a4.z; a_[i][3] = a4.w;
        }
#pragma unroll
        for (int kk = 0; kk < 4; kk++) {
#pragma unroll
            for (int j = 0; j < 4; j++) {
                float4 w = ld4(&W[(k + kk) * HD + (tx + 32 * j) * 4]);
#pragma unroll
                for (int i = 0; i < 4; i++) {
                    acc[i][j].x += a_[i][kk] * w.x;
                    acc[i][j].y += a_[i][kk] * w.y;
                    acc[i][j].z += a_[i][kk] * w.z;
                    acc[i][j].w += a_[i][kk] * w.w;
                }
            }
        }
    }

#pragma unroll
    for (int j = 0; j < 4; j++) {
        float4 bb = ld4(&b[(tx + 32 * j) * 4]);
        float4 w3 = make_float4(0.f, 0.f, 0.f, 0.f);
        if (LAST) w3 = ld4(&W3[(tx + 32 * j) * 4]);
#pragma unroll
        for (int i = 0; i < 4; i++) {
            int r = ty + 8 * i;
            float4 v;
            v.x = tanhf(acc[i][j].x + bb.x);
            v.y = tanhf(acc[i][j].y + bb.y);
            v.z = tanhf(acc[i][j].z + bb.z);
            v.w = tanhf(acc[i][j].w + bb.w);
            if (LAST) {
                v.x = (1.f - v.x * v.x) * w3.x;
                v.y = (1.f - v.y * v.y) * w3.y;
                v.z = (1.f - v.z * v.z) * w3.z;
                v.w = (1.f - v.w * v.w) * w3.w;
            }
            *reinterpret_cast<float4*>(&out[r * HD + (tx + 32 * j) * 4]) = v;
        }
    }
}

// Backward layer: g[r][c] = sum_k din[r][k] * W[c*HD + k]; then
// hbuf[r][c] (holding activation h) is overwritten with g * (1 - h*h).
// din and hbuf are distinct smem buffers; each thread reads/writes hbuf only at
// its own (r,c) positions, so no intra-layer race.
__device__ __forceinline__ void bwd_layer(
    const float* __restrict__ din,
    const float* __restrict__ W,
    float* __restrict__ hbuf,
    int tx, int ty)
{
    float acc[4][16];
#pragma unroll
    for (int i = 0; i < 4; i++)
#pragma unroll
        for (int jj = 0; jj < 16; jj++)
            acc[i][jj] = 0.f;

    for (int k = 0; k < HD; k += 4) {
        float a_[4][4];
#pragma unroll
        for (int i = 0; i < 4; i++) {
            float4 a4 = ld4(&din[(ty + 8 * i) * HD + k]);
            a_[i][0] = a4.x; a_[i][1] = a4.y; a_[i][2] = a4.z; a_[i][3] = a4.w;
        }
#pragma unroll
        for (int jj = 0; jj < 16; jj++) {
            int c = tx + 32 * jj;
            float4 w = ld4(&W[c * HD + k]);
#pragma unroll
            for (int i = 0; i < 4; i++) {
                acc[i][jj] += a_[i][0] * w.x + a_[i][1] * w.y
                            + a_[i][2] * w.z + a_[i][3] * w.w;
            }
        }
    }

#pragma unroll
    for (int jj = 0; jj < 16; jj++) {
        int c = tx + 32 * jj;
#pragma unroll
        for (int i = 0; i < 4; i++) {
            int r = ty + 8 * i;
            float h = hbuf[r * HD + c];
            hbuf[r * HD + c] = acc[i][jj] * (1.f - h * h);
        }
    }
}

__global__ void __launch_bounds__(NT)
hnn_fused_kernel(
    const float* __restrict__ x,
    const float* __restrict__ W0, const float* __restrict__ b0,
    const float* __restrict__ W1, const float* __restrict__ b1,
    const float* __restrict__ W2, const float* __restrict__ b2,
    const float* __restrict__ W3,
    float* __restrict__ out)
{
    extern __shared__ float smem[];
    float* xs = smem;                  // [32][64]
    float* h0 = smem + ROWS * DD;      // [32][512]
    float* h1 = h0 + ROWS * HD;        // [32][512]
    float* dbuf = h1 + ROWS * HD;      // [32][512]

    const int tid = threadIdx.x;
    const int tx = tid & 31;
    const int ty = tid >> 5;
    const long base_row = (long)blockIdx.x * ROWS;

    // load x tile: 2048 floats = 512 float4, 2 per thread
    {
        const float4* xg = reinterpret_cast<const float4*>(x + base_row * DD);
        float4* xsv = reinterpret_cast<float4*>(xs);
#pragma unroll
        for (int idx = tid; idx < ROWS * DD / 4; idx += NT)
            xsv[idx] = xg[idx];
    }
    __syncthreads();

    // forward
    fwd_layer<DD, false>(xs, W0, b0, nullptr, h0, tx, ty);
    __syncthreads();
    fwd_layer<HD, false>(h0, W1, b1, nullptr, h1, tx, ty);
    __syncthreads();
    fwd_layer<HD, true >(h1, W2, b2, W3, dbuf, tx, ty);   // dbuf <- d2
    __syncthreads();

    // backward
    bwd_layer(dbuf, W2, h1, tx, ty);   // h1 <- d1
    __syncthreads();
    bwd_layer(h1, W1, h0, tx, ty);     // h0 <- d0
    __syncthreads();

    // final: gradH[r][c] = sum_k d0[r][k] * W0[c*HD + k], c in [0,64)
    // symplectic output: out[:, 0:32] = gradH[:, 32:64]; out[:, 32:64] = -gradH[:, 0:32]
    {
        float acc[4][2];
#pragma unroll
        for (int i = 0; i < 4; i++) { acc[i][0] = 0.f; acc[i][1] = 0.f; }

        for (int k = 0; k < HD; k += 4) {
            float a_[4][4];
#pragma unroll
            for (int i = 0; i < 4; i++) {
                float4 a4 = ld4(&h0[(ty + 8 * i) * HD + k]);
                a_[i][0] = a4.x; a_[i][1] = a4.y; a_[i][2] = a4.z; a_[i][3] = a4.w;
            }
#pragma unroll
            for (int j = 0; j < 2; j++) {
                int c = tx + 32 * j;
                float4 w = ld4(&W0[c * HD + k]);
#pragma unroll
                for (int i = 0; i < 4; i++) {
                    acc[i][j] += a_[i][0] * w.x + a_[i][1] * w.y
                               + a_[i][2] * w.z + a_[i][3] * w.w;
                }
            }
        }

#pragma unroll
        for (int i = 0; i < 4; i++) {
            long rg = base_row + ty + 8 * i;
            // gradH col (tx)      -> out col (tx+32), negated
            // gradH col (tx + 32) -> out col (tx), positive
            out[rg * DD + tx + 32] = -acc[i][0];
            out[rg * DD + tx]      =  acc[i][1];
        }
    }
}

extern "C" void kernel_launch(void* const* d_in, const int* in_sizes, int n_in,
                              void* d_out, int out_size)
{
    // metadata order: t, x, W0, b0, W1, b1, W2, b2, W3, b3
    const float* x  = (const float*)d_in[1];
    const float* W0 = (const float*)d_in[2];
    const float* b0 = (const float*)d_in[3];
    const float* W1 = (const float*)d_in[4];
    const float* b1 = (const float*)d_in[5];
    const float* W2 = (const float*)d_in[6];
    const float* b2 = (const float*)d_in[7];
    const float* W3 = (const float*)d_in[8];
    float* out = (float*)d_out;

    const int B = in_sizes[1] / DD;    // 65536
    const int smem_bytes = (ROWS * DD + 3 * ROWS * HD) * sizeof(float); // 204800

    cudaFuncSetAttribute(hnn_fused_kernel,
                         cudaFuncAttributeMaxDynamicSharedMemorySize, smem_bytes);

    dim3 grid(B / ROWS);   // 2048
    dim3 block(NT);
    hnn_fused_kernel<<<grid, block, smem_bytes>>>(
        x, W0, b0, W1, b1, W2, b2, W3, out);
}

// round 2
// speedup vs baseline: 4.3067x; 4.3067x over previous
#include <cuda_runtime.h>

#define HD 512
#define DD 64
#define ROWS 32
#define NT 512

// Transposed weights (filled by transpose kernels each launch).
__device__ float g_W1T[HD * HD];   // W1T[k][c] = W1[c][k]
__device__ float g_W2T[HD * HD];   // W2T[k][c] = W2[c][k]
__device__ float g_W0T[HD * DD];   // W0T[h][d] = W0[d][h]

__device__ __forceinline__ float4 ld4(const float* __restrict__ p) {
    return *reinterpret_cast<const float4*>(p);
}

// Tiled transpose: in[R][C] -> out[C][R]
__global__ void tr_kernel(const float* __restrict__ in, float* __restrict__ out,
                          int R, int C) {
    __shared__ float t[32][33];
    int x = blockIdx.x * 32 + threadIdx.x;   // col of in
    int y = blockIdx.y * 32 + threadIdx.y;   // row of in
#pragma unroll
    for (int dy = 0; dy < 32; dy += 8)
        if (y + dy < R && x < C)
            t[threadIdx.y + dy][threadIdx.x] = in[(y + dy) * C + x];
    __syncthreads();
    int xo = blockIdx.y * 32 + threadIdx.x;  // col of out (= row of in)
    int yo = blockIdx.x * 32 + threadIdx.y;  // row of out (= col of in)
#pragma unroll
    for (int dy = 0; dy < 32; dy += 8)
        if (yo + dy < C && xo < R)
            out[(yo + dy) * R + xo] = t[threadIdx.x][threadIdx.y + dy];
}

// GEMM tile: acc[i][j] (rows rg+8i, float4-cols cl+64j) over prev[ROWS][K]
// (smem, broadcast loads) x W[K][HD] (global, coalesced 512B/warp).
template<int K>
__device__ __forceinline__ void gemm_tile(
    const float* __restrict__ prev, const float* __restrict__ W,
    float4 acc[4][2], int cl, int rg)
{
#pragma unroll
    for (int i = 0; i < 4; i++)
#pragma unroll
        for (int j = 0; j < 2; j++)
            acc[i][j] = make_float4(0.f, 0.f, 0.f, 0.f);

#pragma unroll 4
    for (int k = 0; k < K; k += 4) {
        float a_[4][4];
#pragma unroll
        for (int i = 0; i < 4; i++) {
            float4 a4 = ld4(&prev[(rg + 8 * i) * K + k]);
            a_[i][0] = a4.x; a_[i][1] = a4.y; a_[i][2] = a4.z; a_[i][3] = a4.w;
        }
#pragma unroll
        for (int kk = 0; kk < 4; kk++) {
#pragma unroll
            for (int j = 0; j < 2; j++) {
                float4 w = ld4(&W[(k + kk) * HD + (cl + 64 * j) * 4]);
#pragma unroll
                for (int i = 0; i < 4; i++) {
                    acc[i][j].x += a_[i][kk] * w.x;
                    acc[i][j].y += a_[i][kk] * w.y;
                    acc[i][j].z += a_[i][kk] * w.z;
                    acc[i][j].w += a_[i][kk] * w.w;
                }
            }
        }
    }
}

__global__ void __launch_bounds__(NT, 1)
hnn_fused_kernel(
    const float* __restrict__ x,
    const float* __restrict__ W0, const float* __restrict__ b0,
    const float* __restrict__ W1, const float* __restrict__ b1,
    const float* __restrict__ W2, const float* __restrict__ b2,
    const float* __restrict__ W3,
    float* __restrict__ out)
{
    extern __shared__ float smem[];
    float* h0   = smem;                 // [32][512]
    float* h1   = smem + ROWS * HD;     // [32][512]
    float* dbuf = smem + 2 * ROWS * HD; // [32][512], first 2048 floats alias xs
    float* xs   = dbuf;                 // [32][64]

    const int tid = threadIdx.x;
    const int cl = tid & 63;            // column lane: float4-col = cl + 64*j
    const int rg = tid >> 6;            // row group: rows rg + 8*i
    const long base_row = (long)blockIdx.x * ROWS;

    // load x tile: 2048 floats = 512 float4, one per thread (coalesced)
    {
        const float4* xg = reinterpret_cast<const float4*>(x + base_row * DD);
        reinterpret_cast<float4*>(xs)[tid] = xg[tid];
    }
    __syncthreads();

    float4 acc[4][2];

    // L0: h0 = tanh(xs @ W0 + b0)
    gemm_tile<DD>(xs, W0, acc, cl, rg);
#pragma unroll
    for (int j = 0; j < 2; j++) {
        float4 bb = ld4(&b0[(cl + 64 * j) * 4]);
#pragma unroll
        for (int i = 0; i < 4; i++) {
            float4 v;
            v.x = tanhf(acc[i][j].x + bb.x);
            v.y = tanhf(acc[i][j].y + bb.y);
            v.z = tanhf(acc[i][j].z + bb.z);
            v.w = tanhf(acc[i][j].w + bb.w);
            *reinterpret_cast<float4*>(&h0[(rg + 8 * i) * HD + (cl + 64 * j) * 4]) = v;
        }
    }
    __syncthreads();

    // L1: h1 = tanh(h0 @ W1 + b1)
    gemm_tile<HD>(h0, W1, acc, cl, rg);
#pragma unroll
    for (int j = 0; j < 2; j++) {
        float4 bb = ld4(&b1[(cl + 64 * j) * 4]);
#pragma unroll
        for (int i = 0; i < 4; i++) {
            float4 v;
            v.x = tanhf(acc[i][j].x + bb.x);
            v.y = tanhf(acc[i][j].y + bb.y);
            v.z = tanhf(acc[i][j].z + bb.z);
            v.w = tanhf(acc[i][j].w + bb.w);
            *reinterpret_cast<float4*>(&h1[(rg + 8 * i) * HD + (cl + 64 * j) * 4]) = v;
        }
    }
    __syncthreads();

    // L2 + seed of backward: dbuf = (1 - tanh^2(h1@W2 + b2)) * W3  (= d2)
    gemm_tile<HD>(h1, W2, acc, cl, rg);
#pragma unroll
    for (int j = 0; j < 2; j++) {
        float4 bb = ld4(&b2[(cl + 64 * j) * 4]);
        float4 w3 = ld4(&W3[(cl + 64 * j) * 4]);
#pragma unroll
        for (int i = 0; i < 4; i++) {
            float4 v;
            v.x = tanhf(acc[i][j].x + bb.x);
            v.y = tanhf(acc[i][j].y + bb.y);
            v.z = tanhf(acc[i][j].z + bb.z);
            v.w = tanhf(acc[i][j].w + bb.w);
            v.x = (1.f - v.x * v.x) * w3.x;
            v.y = (1.f - v.y * v.y) * w3.y;
            v.z = (1.f - v.z * v.z) * w3.z;
            v.w = (1.f - v.w * v.w) * w3.w;
            *reinterpret_cast<float4*>(&dbuf[(rg + 8 * i) * HD + (cl + 64 * j) * 4]) = v;
        }
    }
    __syncthreads();

    // B2: h1 <- (dbuf @ W2T) * (1 - h1^2)   (in-place, own positions only)
    gemm_tile<HD>(dbuf, g_W2T, acc, cl, rg);
#pragma unroll
    for (int j = 0; j < 2; j++)
#pragma unroll
        for (int i = 0; i < 4; i++) {
            float4* p = reinterpret_cast<float4*>(&h1[(rg + 8 * i) * HD + (cl + 64 * j) * 4]);
            float4 h = *p;
            float4 v;
            v.x = acc[i][j].x * (1.f - h.x * h.x);
            v.y = acc[i][j].y * (1.f - h.y * h.y);
            v.z = acc[i][j].z * (1.f - h.z * h.z);
            v.w = acc[i][j].w * (1.f - h.w * h.w);
            *p = v;
        }
    __syncthreads();

    // B1: h0 <- (h1 @ W1T) * (1 - h0^2)
    gemm_tile<HD>(h1, g_W1T, acc, cl, rg);
#pragma unroll
    for (int j = 0; j < 2; j++)
#pragma unroll
        for (int i = 0; i < 4; i++) {
            float4* p = reinterpret_cast<float4*>(&h0[(rg + 8 * i) * HD + (cl + 64 * j) * 4]);
            float4 h = *p;
            float4 v;
            v.x = acc[i][j].x * (1.f - h.x * h.x);
            v.y = acc[i][j].y * (1.f - h.y * h.y);
            v.z = acc[i][j].z * (1.f - h.z * h.z);
            v.w = acc[i][j].w * (1.f - h.w * h.w);
            *p = v;
        }
    __syncthreads();

    // Final: gradH[r][c] = sum_k d0[r][k] * W0T[k][c], c = cl in [0,64)
    {
        float accf[4] = {0.f, 0.f, 0.f, 0.f};
        for (int k = 0; k < HD; k += 4) {
            float av[4][4];
#pragma unroll
            for (int i = 0; i < 4; i++) {
                float4 a4 = ld4(&h0[(rg + 8 * i) * HD + k]);
                av[i][0] = a4.x; av[i][1] = a4.y; av[i][2] = a4.z; av[i][3] = a4.w;
            }
#pragma unroll
            for (int kk = 0; kk < 4; kk++) {
                float w = g_W0T[(k + kk) * DD + cl];
#pragma unroll
                for (int i = 0; i < 4; i++)
                    accf[i] += av[i][kk] * w;
            }
        }
        // symplectic: out[:,cl+32] = -gradH[:,cl] (cl<32); out[:,cl-32] = gradH[:,cl] (cl>=32)
        const int oc = (cl + 32) & 63;
        const float sgn = (cl < 32) ? -1.f : 1.f;
#pragma unroll
        for (int i = 0; i < 4; i++) {
            long rgl = base_row + rg + 8 * i;
            out[rgl * DD + oc] = sgn * accf[i];
        }
    }
}

extern "C" void kernel_launch(void* const* d_in, const int* in_sizes, int n_in,
                              void* d_out, int out_size)
{
    // metadata order: t, x, W0, b0, W1, b1, W2, b2, W3, b3
    const float* x  = (const float*)d_in[1];
    const float* W0 = (const float*)d_in[2];
    const float* b0 = (const float*)d_in[3];
    const float* W1 = (const float*)d_in[4];
    const float* b1 = (const float*)d_in[5];
    const float* W2 = (const float*)d_in[6];
    const float* b2 = (const float*)d_in[7];
    const float* W3 = (const float*)d_in[8];
    float* out = (float*)d_out;

    float *pW1T, *pW2T, *pW0T;
    cudaGetSymbolAddress((void**)&pW1T, g_W1T);
    cudaGetSymbolAddress((void**)&pW2T, g_W2T);
    cudaGetSymbolAddress((void**)&pW0T, g_W0T);

    dim3 tb(32, 8);
    tr_kernel<<<dim3(HD / 32, HD / 32), tb>>>(W1, pW1T, HD, HD);
    tr_kernel<<<dim3(HD / 32, HD / 32), tb>>>(W2, pW2T, HD, HD);
    tr_kernel<<<dim3(HD / 32, DD / 32), tb>>>(W0, pW0T, DD, HD);

    const int B = in_sizes[1] / DD;  // 65536
    const int smem_bytes = 3 * ROWS * HD * sizeof(float);  // 196608

    cudaFuncSetAttribute(hnn_fused_kernel,
                         cudaFuncAttributeMaxDynamicSharedMemorySize, smem_bytes);

    hnn_fused_kernel<<<B / ROWS, NT, smem_bytes>>>(
        x, W0, b0, W1, b1, W2, b2, W3, out);
}